// round 17
// baseline (speedup 1.0000x reference)
#include <cuda_runtime.h>
#include <cuda_bf16.h>
#include <math.h>
#include <stdint.h>

#define NV 7
#define CIN 512
#define HH 64
#define WW 112
#define HWSZ (HH*WW)
#define DM 128
#define PP 36864
#define OC 64
#define BNEPS 1e-5f
#define PR0 512
#define PROWS 81024

__device__ __nv_bfloat16 g_feat[NV * HWSZ * DM];
__device__ float g_fused[PP * DM];
__device__ __nv_bfloat16 g_h2p[(size_t)PROWS * 128];
__device__ __nv_bfloat16 g_wt[125 * OC * DM];   // [tap][o][c], bf16

__device__ __forceinline__ uint32_t smem_u32(const void* p) {
    uint32_t a;
    asm("{ .reg .u64 t; cvta.to.shared.u64 t, %1; cvt.u32.u64 %0, t; }" : "=r"(a) : "l"(p));
    return a;
}
__device__ __forceinline__ void cp16(uint32_t dst, const void* src) {
    asm volatile("cp.async.cg.shared.global [%0], [%1], 16;" :: "r"(dst), "l"(src));
}
__device__ __forceinline__ void mma8(float* d, const uint32_t* a, const uint32_t* b) {
    asm volatile(
        "mma.sync.aligned.m16n8k8.row.col.f32.tf32.tf32.f32 "
        "{%0,%1,%2,%3},{%4,%5,%6,%7},{%8,%9},{%0,%1,%2,%3};"
        : "+f"(d[0]), "+f"(d[1]), "+f"(d[2]), "+f"(d[3])
        : "r"(a[0]), "r"(a[1]), "r"(a[2]), "r"(a[3]), "r"(b[0]), "r"(b[1]));
}
__device__ __forceinline__ void mma16(float* d, const uint32_t* a, const uint32_t* b) {
    asm volatile(
        "mma.sync.aligned.m16n8k16.row.col.f32.bf16.bf16.f32 "
        "{%0,%1,%2,%3},{%4,%5,%6,%7},{%8,%9},{%0,%1,%2,%3};"
        : "+f"(d[0]), "+f"(d[1]), "+f"(d[2]), "+f"(d[3])
        : "r"(a[0]), "r"(a[1]), "r"(a[2]), "r"(a[3]), "r"(b[0]), "r"(b[1]));
}
#define LDSM4(r0, r1, r2, r3, addr) \
    asm volatile("ldmatrix.sync.aligned.m8n8.x4.shared.b16 {%0,%1,%2,%3}, [%4];" \
        : "=r"(r0), "=r"(r1), "=r"(r2), "=r"(r3) : "r"(addr))

// ---------- zero halo of padded volume ----------
__global__ void k_zero() {
    size_t i = (size_t)blockIdx.x * 256 + threadIdx.x;
    if (i >= (size_t)PROWS * 16) return;
    int r = (int)(i >> 4);
    int pr = r - PR0;
    if (pr >= 0 && pr < 80000) {
        int zp = pr / 10000, rem = pr % 10000, yp = rem / 100, xp = rem % 100;
        if (zp >= 2 && zp < 6 && yp >= 2 && yp < 98 && xp >= 2 && xp < 98) return;
    }
    ((uint4*)g_h2p)[i] = make_uint4(0u, 0u, 0u, 0u);
}
// ---------- weight prep ----------
__global__ void k_wt(const float* __restrict__ w3b) {
    int idx = blockIdx.x * 256 + threadIdx.x;
    if (idx >= 125 * 8192) return;
    int t = idx >> 13, o = (idx >> 7) & 63, c = idx & 127;
    g_wt[idx] = __float2bfloat16_rn(w3b[(size_t)(o * 128 + c) * 125 + t]);
}

// ---------- k1: projection GEMM, cp.async 2-stage pipeline, tf32 mma ----------
#define K1_A_F 4352
#define K1_B_F 4608
#define SMEM_K1 ((2 * K1_A_F + 2 * K1_B_F) * 4)
__global__ __launch_bounds__(256) void k1_mma(
    const float* __restrict__ img, const float* __restrict__ wproj, const float* __restrict__ bproj,
    const float* __restrict__ g1, const float* __restrict__ bb1,
    const float* __restrict__ m1, const float* __restrict__ v1)
{
    extern __shared__ __align__(16) float s1[];
    float* sAb = s1;
    float* sBb = s1 + 2 * K1_A_F;
    const uint32_t sAu = smem_u32(sAb);
    const uint32_t sBu = smem_u32(sBb);

    const int tid = threadIdx.x;
    const int lane = tid & 31, wid = tid >> 5;
    const int gq = lane >> 2, tq = lane & 3;
    const int wm = wid >> 1, wn = wid & 1;
    const int m0 = blockIdx.x * 128;
    const int n = m0 / HWSZ, hw0 = m0 % HWSZ;
    const float* ibase = img + (size_t)n * CIN * HWSZ + hw0;

    float acc[2][8][4];
    #pragma unroll
    for (int mt = 0; mt < 2; mt++)
        #pragma unroll
        for (int nt = 0; nt < 8; nt++)
            #pragma unroll
            for (int q = 0; q < 4; q++) acc[mt][nt][q] = 0.f;

    {
        const float* asrc = ibase;
        #pragma unroll
        for (int i = tid; i < 1024; i += 256)
            cp16(sAu + (uint32_t)((i >> 5) * 136 + (i & 31) * 4) * 4, asrc + (size_t)(i >> 5) * HWSZ + (i & 31) * 4);
        #pragma unroll
        for (int i = tid; i < 1024; i += 256)
            cp16(sBu + (uint32_t)((i >> 3) * 36 + (i & 7) * 4) * 4, wproj + (size_t)(i >> 3) * CIN + (i & 7) * 4);
        asm volatile("cp.async.commit_group;" ::: "memory");
    }

    for (int t = 0; t < 16; t++) {
        const int buf = t & 1;
        if (t < 15) {
            const int k1 = (t + 1) * 32;
            const int nb = (t + 1) & 1;
            const float* asrc = ibase + (size_t)k1 * HWSZ;
            #pragma unroll
            for (int i = tid; i < 1024; i += 256)
                cp16(sAu + (uint32_t)(nb * K1_A_F + (i >> 5) * 136 + (i & 31) * 4) * 4,
                     asrc + (size_t)(i >> 5) * HWSZ + (i & 31) * 4);
            #pragma unroll
            for (int i = tid; i < 1024; i += 256)
                cp16(sBu + (uint32_t)(nb * K1_B_F + (i >> 3) * 36 + (i & 7) * 4) * 4,
                     wproj + (size_t)(i >> 3) * CIN + k1 + (i & 7) * 4);
            asm volatile("cp.async.commit_group;" ::: "memory");
            asm volatile("cp.async.wait_group 1;" ::: "memory");
        } else {
            asm volatile("cp.async.wait_group 0;" ::: "memory");
        }
        __syncthreads();
        const float* sA = sAb + buf * K1_A_F;
        const float* sB = sBb + buf * K1_B_F;
        #pragma unroll
        for (int ks = 0; ks < 4; ks++) {
            const int k = ks * 8;
            uint32_t a[2][4], b[8][2];
            #pragma unroll
            for (int mt = 0; mt < 2; mt++) {
                int row = wm * 32 + mt * 16 + gq;
                a[mt][0] = __float_as_uint(sA[(k + tq) * 136 + row]);
                a[mt][1] = __float_as_uint(sA[(k + tq) * 136 + row + 8]);
                a[mt][2] = __float_as_uint(sA[(k + tq + 4) * 136 + row]);
                a[mt][3] = __float_as_uint(sA[(k + tq + 4) * 136 + row + 8]);
            }
            #pragma unroll
            for (int nt = 0; nt < 8; nt++) {
                int dc = wn * 64 + nt * 8 + gq;
                b[nt][0] = __float_as_uint(sB[dc * 36 + k + tq]);
                b[nt][1] = __float_as_uint(sB[dc * 36 + k + tq + 4]);
            }
            #pragma unroll
            for (int mt = 0; mt < 2; mt++)
                #pragma unroll
                for (int nt = 0; nt < 8; nt++)
                    mma8(acc[mt][nt], a[mt], b[nt]);
        }
        __syncthreads();
    }
    float scv[8][2], shv[8][2];
    #pragma unroll
    for (int nt = 0; nt < 8; nt++) {
        #pragma unroll
        for (int j = 0; j < 2; j++) {
            int d = wn * 64 + nt * 8 + 2 * tq + j;
            float s = g1[d] * rsqrtf(v1[d] + BNEPS);
            scv[nt][j] = s;
            shv[nt][j] = (bproj[d] - m1[d]) * s + bb1[d];
        }
    }
    #pragma unroll
    for (int mt = 0; mt < 2; mt++) {
        #pragma unroll
        for (int h = 0; h < 2; h++) {
            int m = m0 + wm * 32 + mt * 16 + gq + h * 8;
            __nv_bfloat16* dst = g_feat + (size_t)m * DM + wn * 64 + 2 * tq;
            #pragma unroll
            for (int nt = 0; nt < 8; nt++) {
                float vx = fmaxf(acc[mt][nt][h * 2 + 0] * scv[nt][0] + shv[nt][0], 0.f);
                float vy = fmaxf(acc[mt][nt][h * 2 + 1] * scv[nt][1] + shv[nt][1], 0.f);
                *(__nv_bfloat162*)(dst + nt * 8) = __floats2bfloat162_rn(vx, vy);
            }
        }
    }
}

// ---------- k2: gather (bf16) + masked softmax fusion, 4 voxels/block ----------
__global__ __launch_bounds__(512) void k2_fuse(
    const int* __restrict__ xi, const int* __restrict__ yi, const int* __restrict__ valid)
{
    __shared__ int slin[4][NV];
    const int tid = threadIdx.x;
    const int sub = tid >> 7, d = tid & 127;
    const int p = blockIdx.x * 4 + sub;
    if (tid < 4 * NV) {
        int s = tid / NV, n = tid % NV;
        int pp = blockIdx.x * 4 + s;
        int v = valid[n * PP + pp];
        slin[s][n] = v ? (yi[n * PP + pp] * WW + xi[n * PP + pp]) : -1;
    }
    __syncthreads();
    float vv[NV];
    #pragma unroll
    for (int n = 0; n < NV; n++) {
        int lin = slin[sub][n];
        float val = 0.f;
        if (lin >= 0)
            val = __bfloat162float(g_feat[((size_t)(n * HWSZ + lin)) * DM + d]);
        vv[n] = val;
    }
    float mx = vv[0];
    #pragma unroll
    for (int n = 1; n < NV; n++) mx = fmaxf(mx, vv[n]);
    float s = 0.f, ws = 0.f;
    #pragma unroll
    for (int n = 0; n < NV; n++) { float e = __expf(vv[n] - mx); s += e; ws += e * vv[n]; }
    g_fused[(size_t)p * DM + d] = ws / s;
}

// ---------- k3: 1x1 GEMM via mma.sync tf32 + BN2 + ReLU -> padded bf16 volume ----------
__global__ __launch_bounds__(256) void k3_mma(
    const float* __restrict__ w3a, const float* __restrict__ b3a,
    const float* __restrict__ g2, const float* __restrict__ bb2,
    const float* __restrict__ m2, const float* __restrict__ v2)
{
    __shared__ float sA[128][36];
    __shared__ float sB[128][36];
    const int tid = threadIdx.x;
    const int lane = tid & 31, wid = tid >> 5;
    const int gq = lane >> 2, tq = lane & 3;
    const int wm = wid >> 1, wn = wid & 1;
    const int m0 = blockIdx.x * 128;

    float acc[2][8][4];
    #pragma unroll
    for (int mt = 0; mt < 2; mt++)
        #pragma unroll
        for (int nt = 0; nt < 8; nt++)
            #pragma unroll
            for (int q = 0; q < 4; q++) acc[mt][nt][q] = 0.f;

    for (int k0 = 0; k0 < DM; k0 += 32) {
        __syncthreads();
        #pragma unroll 4
        for (int i = tid; i < 4096; i += 256) {
            int mm = i >> 5, kk = i & 31;
            sA[mm][kk] = g_fused[(size_t)(m0 + mm) * DM + k0 + kk];
            sB[mm][kk] = w3a[(size_t)mm * DM + k0 + kk];
        }
        __syncthreads();
        #pragma unroll
        for (int ks = 0; ks < 4; ks++) {
            const int k = ks * 8;
            uint32_t a[2][4], b[8][2];
            #pragma unroll
            for (int mt = 0; mt < 2; mt++) {
                const float* p = &sA[wm * 32 + mt * 16 + gq][k + tq];
                a[mt][0] = __float_as_uint(p[0]);
                a[mt][1] = __float_as_uint(p[8 * 36]);
                a[mt][2] = __float_as_uint(p[4]);
                a[mt][3] = __float_as_uint(p[8 * 36 + 4]);
            }
            #pragma unroll
            for (int nt = 0; nt < 8; nt++) {
                const float* p = &sB[wn * 64 + nt * 8 + gq][k + tq];
                b[nt][0] = __float_as_uint(p[0]);
                b[nt][1] = __float_as_uint(p[4]);
            }
            #pragma unroll
            for (int mt = 0; mt < 2; mt++)
                #pragma unroll
                for (int nt = 0; nt < 8; nt++)
                    mma8(acc[mt][nt], a[mt], b[nt]);
        }
    }
    float scv[8][2], shv[8][2];
    #pragma unroll
    for (int nt = 0; nt < 8; nt++) {
        #pragma unroll
        for (int j = 0; j < 2; j++) {
            int d = wn * 64 + nt * 8 + 2 * tq + j;
            float s = g2[d] * rsqrtf(v2[d] + BNEPS);
            scv[nt][j] = s;
            shv[nt][j] = (b3a[d] - m2[d]) * s + bb2[d];
        }
    }
    #pragma unroll
    for (int mt = 0; mt < 2; mt++) {
        #pragma unroll
        for (int h = 0; h < 2; h++) {
            int m = m0 + wm * 32 + mt * 16 + gq + h * 8;
            int z = m / 9216, rem = m % 9216, y = rem / 96, x = rem % 96;
            size_t pm = (size_t)(z + 2) * 10000 + (y + 2) * 100 + (x + 2) + PR0;
            __nv_bfloat16* dst = g_h2p + pm * 128 + wn * 64 + 2 * tq;
            #pragma unroll
            for (int nt = 0; nt < 8; nt++) {
                float vx = fmaxf(acc[mt][nt][h * 2 + 0] * scv[nt][0] + shv[nt][0], 0.f);
                float vy = fmaxf(acc[mt][nt][h * 2 + 1] * scv[nt][1] + shv[nt][1], 0.f);
                *(__nv_bfloat162*)(dst + nt * 8) = __floats2bfloat162_rn(vx, vy);
            }
        }
    }
}

// ---------- k4: conv + fused head (BN3/ReLU/1x1/sigmoid), ldmatrix, cp.async ----------
#define SA_ST 136
#define SB_ST 136
#define SA_BYTES (132 * SA_ST * 2)      // 35904
#define SB_BYTES (64 * SB_ST * 2)       // 17408
#define SMEM_K4 (SA_BYTES + 2 * SB_BYTES)   // 70720
__global__ __launch_bounds__(128, 3) void k4_mma(
    const float* __restrict__ b3b, const float* __restrict__ g3,
    const float* __restrict__ bb3, const float* __restrict__ m3, const float* __restrict__ v3,
    const float* __restrict__ w3c, const float* __restrict__ b3c, float* __restrict__ out)
{
    extern __shared__ __align__(16) char smem[];
    __shared__ float swc[256];
    const uint32_t sbase = smem_u32(smem);
    const uint32_t sAu = sbase;
    const uint32_t sBu0 = sbase + SA_BYTES;

    const int tid = threadIdx.x;
    const int lane = tid & 31, wm = tid >> 5;
    const int gq = lane >> 2, tq = lane & 3;
    const int m0 = 20000 + blockIdx.x * 128;

    #pragma unroll
    for (int i = tid; i < 256; i += 128) swc[i] = w3c[i];

    // slab list (uniform per block)
    int sa_r[25], sa_t[25], ns = 0;
    for (int t = 0; t < 25; t++) {
        int arow0 = m0 + (t / 5 - 2) * 10000 + (t % 5 - 2) * 100 - 2;
        if (arow0 >= 60000 || arow0 + 131 < 20000) continue;
        sa_r[ns] = arow0; sa_t[ns] = t; ns++;
    }

    const int a_row0 = wm * 32 + ((lane >> 3) & 1) * 8 + (lane & 7);
    const uint32_t a_colb = (uint32_t)((lane >> 4) & 1) * 16;
    int b_row[4];
    #pragma unroll
    for (int j = 0; j < 4; j++)
        b_row[j] = 16 * j + (((lane >> 4) & 1) << 3) + (lane & 7);
    const uint32_t b_colb = (uint32_t)((lane >> 3) & 1) * 16;

    float acc[2][8][4];
    #pragma unroll
    for (int mt = 0; mt < 2; mt++)
        #pragma unroll
        for (int nt = 0; nt < 8; nt++)
            #pragma unroll
            for (int q = 0; q < 4; q++) acc[mt][nt][q] = 0.f;

    auto issueA = [&](int arow0) {
        const uint4* src = (const uint4*)(g_h2p) + ((size_t)arow0 + PR0) * 16;
        #pragma unroll 4
        for (int i = tid; i < 132 * 16; i += 128)
            cp16(sAu + (uint32_t)((i >> 4) * SA_ST * 2 + (i & 15) * 16), src + i);
    };
    auto issueB = [&](int tap, uint32_t dst) {
        const uint4* src = (const uint4*)(g_wt) + (size_t)tap * 1024;
        #pragma unroll 4
        for (int i = tid; i < 1024; i += 128)
            cp16(dst + (uint32_t)((i >> 4) * SB_ST * 2 + (i & 15) * 16), src + i);
    };

    int bp = 0;
    // prologue: A(0) + B(slab0, kw0) -> buf0
    issueA(sa_r[0]);
    issueB(sa_t[0] * 5, sBu0);
    asm volatile("cp.async.commit_group;" ::: "memory");

    for (int s = 0; s < ns; s++) {
        if (s > 0) {
            __syncthreads();   // all warps done with previous A
            issueA(sa_r[s]);
            asm volatile("cp.async.commit_group;" ::: "memory");
        }
        asm volatile("cp.async.wait_group 0;" ::: "memory");
        __syncthreads();
        const int tap0 = sa_t[s] * 5;
        for (int kw = 0; kw < 5; kw++) {
            if (kw < 4) {
                issueB(tap0 + kw + 1, sBu0 + (uint32_t)((bp + kw + 1) & 1) * SB_BYTES);
                asm volatile("cp.async.commit_group;" ::: "memory");
            } else if (s + 1 < ns) {
                issueB(sa_t[s + 1] * 5, sBu0 + (uint32_t)(bp ^ 1) * SB_BYTES);
                asm volatile("cp.async.commit_group;" ::: "memory");
            }
            const uint32_t curBu = sBu0 + (uint32_t)((bp + kw) & 1) * SB_BYTES;
            const uint32_t aw0 = sAu + (uint32_t)(a_row0 + kw) * (SA_ST * 2) + a_colb;
            const uint32_t aw1 = aw0 + 16u * (SA_ST * 2);
            uint32_t bw[4];
            #pragma unroll
            for (int j = 0; j < 4; j++)
                bw[j] = curBu + (uint32_t)b_row[j] * (SB_ST * 2) + b_colb;
            #pragma unroll 2
            for (int ks = 0; ks < 8; ks++) {
                const uint32_t k0b = (uint32_t)ks * 32;
                uint32_t a[2][4], b[8][2];
                LDSM4(a[0][0], a[0][1], a[0][2], a[0][3], aw0 + k0b);
                LDSM4(a[1][0], a[1][1], a[1][2], a[1][3], aw1 + k0b);
                #pragma unroll
                for (int j = 0; j < 4; j++) {
                    uint32_t r0, r1, r2, r3;
                    LDSM4(r0, r1, r2, r3, bw[j] + k0b);
                    b[2 * j][0] = r0; b[2 * j][1] = r1;
                    b[2 * j + 1][0] = r2; b[2 * j + 1][1] = r3;
                }
                #pragma unroll
                for (int mt = 0; mt < 2; mt++)
                    #pragma unroll
                    for (int nt = 0; nt < 8; nt++)
                        mma16(acc[mt][nt], a[mt], b[nt]);
            }
            if (kw < 4) {
                asm volatile("cp.async.wait_group 0;" ::: "memory");
                __syncthreads();
            }
        }
        bp ^= 1;
    }

    // fused epilogue: BN3 + ReLU + 1x1 head (quad shuffle-reduce) + sigmoid
    float scv[8][2], shv[8][2];
    #pragma unroll
    for (int nt = 0; nt < 8; nt++) {
        #pragma unroll
        for (int j = 0; j < 2; j++) {
            int oc = nt * 8 + 2 * tq + j;
            float s = g3[oc] * rsqrtf(v3[oc] + BNEPS);
            scv[nt][j] = s;
            shv[nt][j] = (b3b[oc] - m3[oc]) * s + bb3[oc];
        }
    }
    const float bc0 = b3c[0], bc1 = b3c[1], bc2 = b3c[2], bc3 = b3c[3];
    #pragma unroll
    for (int mt = 0; mt < 2; mt++) {
        #pragma unroll
        for (int h = 0; h < 2; h++) {
            int pm = m0 + wm * 32 + mt * 16 + gq + h * 8;
            float p0 = 0.f, p1 = 0.f, p2 = 0.f, p3 = 0.f;
            #pragma unroll
            for (int nt = 0; nt < 8; nt++) {
                #pragma unroll
                for (int j = 0; j < 2; j++) {
                    int oc = nt * 8 + 2 * tq + j;
                    float hv = fmaxf(acc[mt][nt][h * 2 + j] * scv[nt][j] + shv[nt][j], 0.f);
                    p0 += hv * swc[oc];
                    p1 += hv * swc[64 + oc];
                    p2 += hv * swc[128 + oc];
                    p3 += hv * swc[192 + oc];
                }
            }
            #pragma unroll
            for (int off = 1; off < 4; off <<= 1) {
                p0 += __shfl_xor_sync(0xffffffffu, p0, off);
                p1 += __shfl_xor_sync(0xffffffffu, p1, off);
                p2 += __shfl_xor_sync(0xffffffffu, p2, off);
                p3 += __shfl_xor_sync(0xffffffffu, p3, off);
            }
            int zp = pm / 10000, r2 = pm % 10000, yp = r2 / 100, xp = r2 % 100;
            if (tq == 0 && zp >= 2 && zp < 6 && yp >= 2 && yp < 98 && xp >= 2 && xp < 98) {
                int vox = (zp - 2) * 9216 + (yp - 2) * 96 + (xp - 2);
                out[0 * PP + vox] = 1.f / (1.f + __expf(-(p0 + bc0)));
                out[1 * PP + vox] = 1.f / (1.f + __expf(-(p1 + bc1)));
                out[2 * PP + vox] = 1.f / (1.f + __expf(-(p2 + bc2)));
                out[3 * PP + vox] = 1.f / (1.f + __expf(-(p3 + bc3)));
            }
        }
    }
}

extern "C" void kernel_launch(void* const* d_in, const int* in_sizes, int n_in,
                              void* d_out, int out_size)
{
    const float* img = (const float*)d_in[0];
    const int* xi = (const int*)d_in[1];
    const int* yi = (const int*)d_in[2];
    const int* valid = (const int*)d_in[3];
    const float* wproj = (const float*)d_in[4];
    const float* bproj = (const float*)d_in[5];
    const float* bn1g = (const float*)d_in[6];
    const float* bn1b = (const float*)d_in[7];
    const float* bn1m = (const float*)d_in[8];
    const float* bn1v = (const float*)d_in[9];
    const float* w3a = (const float*)d_in[10];
    const float* b3a = (const float*)d_in[11];
    const float* bn2g = (const float*)d_in[12];
    const float* bn2b = (const float*)d_in[13];
    const float* bn2m = (const float*)d_in[14];
    const float* bn2v = (const float*)d_in[15];
    const float* w3b = (const float*)d_in[16];
    const float* b3b = (const float*)d_in[17];
    const float* bn3g = (const float*)d_in[18];
    const float* bn3b = (const float*)d_in[19];
    const float* bn3m = (const float*)d_in[20];
    const float* bn3v = (const float*)d_in[21];
    const float* w3c = (const float*)d_in[22];
    const float* b3c = (const float*)d_in[23];
    float* out = (float*)d_out;

    cudaFuncSetAttribute(k1_mma, cudaFuncAttributeMaxDynamicSharedMemorySize, SMEM_K1);
    cudaFuncSetAttribute(k4_mma, cudaFuncAttributeMaxDynamicSharedMemorySize, SMEM_K4);
    k_zero<<<(PROWS * 16 + 255) / 256, 256>>>();
    k_wt<<<(125 * 8192 + 255) / 256, 256>>>(w3b);
    k1_mma<<<(NV * HWSZ) / 128, 256, SMEM_K1>>>(img, wproj, bproj, bn1g, bn1b, bn1m, bn1v);
    k2_fuse<<<PP / 4, 512>>>(xi, yi, valid);
    k3_mma<<<PP / 128, 256>>>(w3a, b3a, bn2g, bn2b, bn2m, bn2v);
    k4_mma<<<313, 128, SMEM_K4>>>(b3b, bn3g, bn3b, bn3m, bn3v, w3c, b3c, out);
}